// round 4
// baseline (speedup 1.0000x reference)
#include <cuda_runtime.h>
#include <cstdint>

// out[b,h,w,c] = x[b,h,w,c] + (c < 512 ? spatial_pe[h,w,c]
//                                      : pattern_pe[pattern_indices[b,h,w] % 64][c-512])
// x [64,30,30,1024] f32, pattern_indices [64,30,30] i32,
// spatial_pe [30,30,512] f32, pattern_pe [64,512] f32.  H==W==30.
//
// cp.async double-buffered streaming pipeline:
//  - tile = 4 consecutive pixels (16 KB of x). Thread t owns channel chunk t.
//  - per tile each thread issues 4 cp.async.cg (16B) into its PRIVATE smem
//    slots -> outstanding loads cost 0 registers -> high occupancy AND deep MLP.
//  - each thread consumes only bytes it produced -> no __syncthreads at all;
//    cp.async.wait_group gives the per-thread ordering.
//  - 2-buffer pipeline: prefetch tile t+1, wait for tile t, add PE, store.

static constexpr int D4    = 256;    // float4 per pixel
static constexpr int HALF4 = 128;    // spatial/pattern split (float4 units)
static constexpr int HW    = 900;    // 30*30
static constexpr int TPI   = 225;    // tiles per image (900/4)
static constexpr int PPB   = 4;      // pixels per tile
static constexpr int TPB   = 10;     // tiles per block
static constexpr int NTILE = 64 * TPI;          // 14400
static constexpr int NBLK  = NTILE / TPB;       // 1440
static constexpr int NUM_PAT = 64;

__device__ __forceinline__ void cp16(uint32_t dst_smem, const void* src) {
    asm volatile("cp.async.cg.shared.global [%0], [%1], 16;\n"
                 :: "r"(dst_smem), "l"(src));
}
__device__ __forceinline__ void cp_commit() {
    asm volatile("cp.async.commit_group;\n");
}
template <int N> __device__ __forceinline__ void cp_wait() {
    asm volatile("cp.async.wait_group %0;\n" :: "n"(N));
}

__global__ void __launch_bounds__(256)
pe_add_kernel(const float4* __restrict__ x4,
              const int*    __restrict__ pidx,
              const float4* __restrict__ sp4,   // [900, 128] float4
              const float4* __restrict__ pp4,   // [64, 128] float4
              float4*       __restrict__ out4)
{
    __shared__ float4 sbuf[2][PPB][256];        // 32 KB, double-buffered

    const int tid = threadIdx.x;
    const uint32_t sbase = (uint32_t)__cvta_generic_to_shared(&sbuf[0][0][0]);
    const int tile0 = blockIdx.x * TPB;

    // ---- prologue: prefetch tile 0 into buffer 0 ----
    {
        const int tt  = tile0;
        const int b   = tt / TPI;
        const int pix0 = b * HW + (tt - b * TPI) * PPB;
        const long long g0 = (long long)pix0 * D4 + tid;
#pragma unroll
        for (int j = 0; j < PPB; j++)
            cp16(sbase + (uint32_t)((j * 256 + tid) * 16), &x4[g0 + (long long)j * D4]);
        cp_commit();
    }

#pragma unroll 1
    for (int t = 0; t < TPB; t++) {
        const int tt   = tile0 + t;
        const int b    = tt / TPI;
        const int hw0  = (tt - b * TPI) * PPB;
        const int pix0 = b * HW + hw0;

        // ---- prefetch tile t+1 into the other buffer ----
        if (t + 1 < TPB) {
            const int tt1  = tt + 1;
            const int b1   = tt1 / TPI;
            const int pix1 = b1 * HW + (tt1 - b1 * TPI) * PPB;
            const long long g1 = (long long)pix1 * D4 + tid;
            const uint32_t base1 = sbase + (uint32_t)(((t + 1) & 1) * PPB * 256 * 16);
#pragma unroll
            for (int j = 0; j < PPB; j++)
                cp16(base1 + (uint32_t)((j * 256 + tid) * 16), &x4[g1 + (long long)j * D4]);
            cp_commit();
        }

        // ---- PE loads (L2-resident), overlap with cp.async wait ----
        float4 pe[PPB];
        if (tid < HALF4) {                       // warps 0-3: spatial half
            const float4* s = sp4 + (long long)hw0 * HALF4 + tid;
#pragma unroll
            for (int j = 0; j < PPB; j++)
                pe[j] = __ldg(&s[j * HALF4]);
        } else {                                 // warps 4-7: pattern half
            const int c = tid - HALF4;
            const int4 pi = __ldg(reinterpret_cast<const int4*>(pidx + pix0));
            pe[0] = __ldg(&pp4[(long long)(((unsigned)pi.x) % NUM_PAT) * HALF4 + c]);
            pe[1] = __ldg(&pp4[(long long)(((unsigned)pi.y) % NUM_PAT) * HALF4 + c]);
            pe[2] = __ldg(&pp4[(long long)(((unsigned)pi.z) % NUM_PAT) * HALF4 + c]);
            pe[3] = __ldg(&pp4[(long long)(((unsigned)pi.w) % NUM_PAT) * HALF4 + c]);
        }

        // ---- wait for tile t (leave t+1 in flight) ----
        if (t + 1 < TPB) cp_wait<1>(); else cp_wait<0>();

        // ---- consume own smem column, add PE, streaming store ----
        const int buf = t & 1;
        const long long o0 = (long long)pix0 * D4 + tid;
#pragma unroll
        for (int j = 0; j < PPB; j++) {
            float4 v = sbuf[buf][j][tid];
            v.x += pe[j].x; v.y += pe[j].y; v.z += pe[j].z; v.w += pe[j].w;
            __stcs(&out4[o0 + (long long)j * D4], v);
        }
    }
}

extern "C" void kernel_launch(void* const* d_in, const int* in_sizes, int n_in,
                              void* d_out, int out_size)
{
    const float4* x4   = (const float4*)d_in[0];
    const int*    pidx = (const int*)d_in[1];
    const float4* sp4  = (const float4*)d_in[2];
    const float4* pp4  = (const float4*)d_in[3];
    float4*       out4 = (float4*)d_out;

    pe_add_kernel<<<NBLK, 256>>>(x4, pidx, sp4, pp4, out4);  // 1440 blocks
}